// round 6
// baseline (speedup 1.0000x reference)
#include <cuda_runtime.h>
#include <math.h>
#include <stdint.h>

// VQ_Layer: nearest-codebook quantization — FFMA2 (fma.rn.f32x2) build.
// Numerics contract (verified passing in R5, rel_err 8.5e-7):
//  - dot(row, code): sequential k-ascending FMA chain. Here the two rows a
//    thread owns ride in the two lanes of a packed f32x2 chain; each lane is
//    bit-identical to the scalar sequential chain.
//  - |x|^2, |e|^2: square (rounded) then sequential add (rounded), k ascending
//  - dist = (a_sq - 2*dot) single-rounded, then + b_sq rounded
//  - argmin: first index wins ties (strict < ascending scan)
//
//   inputs     [32,64,64,64] fp32  -> flat [131072, 64]
//   embeddings [1024, 64]    fp32
// Output (fp32, concatenated): quantized_st [131072*64], indices [131072],
//                              perplexity [1], vq_loss [1]

typedef unsigned long long ull;

#define N_ROWS 131072
#define D 64
#define K_CODES 1024
#define TILE_K 64                   // duplicated tile: 64 codes * 128 floats = 32KB
#define THREADS 128
#define ROWS_PER_BLOCK 256          // 2 rows per thread (lanes of f32x2)
#define NUM_BLOCKS (N_ROWS / ROWS_PER_BLOCK)   // 512
#define QOFF (N_ROWS * D)           // 8388608

// Scratch (no allocations allowed): device globals.
__device__ float g_norms[K_CODES];
__device__ int   g_hist[K_CODES];
__device__ float g_partial[NUM_BLOCKS];

// ---- packed f32x2 helpers ----
__device__ __forceinline__ void fma2(ull &acc, ull a, ull b) {
    asm("fma.rn.f32x2 %0, %1, %2, %3;" : "=l"(acc) : "l"(a), "l"(b), "l"(acc));
}
__device__ __forceinline__ ull pack2(float lo, float hi) {
    ull r; asm("mov.b64 %0, {%1, %2};" : "=l"(r) : "f"(lo), "f"(hi)); return r;
}
__device__ __forceinline__ void unpack2(ull v, float &lo, float &hi) {
    asm("mov.b64 {%0, %1}, %2;" : "=f"(lo), "=f"(hi) : "l"(v));
}

// Precompute code norms |e_k|^2 (square-then-add, strictly sequential in k)
// and zero the histogram (graph replays must be self-resetting).
__global__ void vq_prep_kernel(const float* __restrict__ emb) {
    int k = blockIdx.x * blockDim.x + threadIdx.x;
    if (k < K_CODES) {
        const float4* e = (const float4*)(emb + (size_t)k * D);
        float s = 0.f;
        #pragma unroll
        for (int i = 0; i < 16; i++) {
            float4 v = e[i];
            s = __fadd_rn(s, __fmul_rn(v.x, v.x));
            s = __fadd_rn(s, __fmul_rn(v.y, v.y));
            s = __fadd_rn(s, __fmul_rn(v.z, v.z));
            s = __fadd_rn(s, __fmul_rn(v.w, v.w));
        }
        g_norms[k] = s;
        g_hist[k]  = 0;
    }
}

__global__ __launch_bounds__(THREADS) void vq_main_kernel(
    const float* __restrict__ inp,
    const float* __restrict__ emb,
    float* __restrict__ out)
{
    // Duplicated code tile: element (c, k) stored at [c*128 + 2k] and [+1],
    // so one LDS.128 yields {e[k],e[k],e[k+1],e[k+1]} for the packed FMA.
    __shared__ __align__(16) float sh_e[TILE_K * 2 * D];   // 32 KB
    __shared__ float sh_norm[TILE_K];
    __shared__ float sh_red[THREADS];

    const int tid = threadIdx.x;
    const int r0 = blockIdx.x * ROWS_PER_BLOCK + tid;
    const int r1 = r0 + THREADS;

    // Load rows, compute |x|^2 sequentially, pack lanes {row0[k], row1[k]}.
    const float4* p0 = (const float4*)(inp + (size_t)r0 * D);
    const float4* p1 = (const float4*)(inp + (size_t)r1 * D);
    float asq0 = 0.f, asq1 = 0.f;
    ull xp[64];
    #pragma unroll
    for (int i = 0; i < 16; i++) {
        float4 a = p0[i];
        float4 b = p1[i];
        asq0 = __fadd_rn(asq0, __fmul_rn(a.x, a.x));
        asq0 = __fadd_rn(asq0, __fmul_rn(a.y, a.y));
        asq0 = __fadd_rn(asq0, __fmul_rn(a.z, a.z));
        asq0 = __fadd_rn(asq0, __fmul_rn(a.w, a.w));
        asq1 = __fadd_rn(asq1, __fmul_rn(b.x, b.x));
        asq1 = __fadd_rn(asq1, __fmul_rn(b.y, b.y));
        asq1 = __fadd_rn(asq1, __fmul_rn(b.z, b.z));
        asq1 = __fadd_rn(asq1, __fmul_rn(b.w, b.w));
        xp[4*i+0] = pack2(a.x, b.x);
        xp[4*i+1] = pack2(a.y, b.y);
        xp[4*i+2] = pack2(a.z, b.z);
        xp[4*i+3] = pack2(a.w, b.w);
    }

    float best0 = 3.402823466e38f, best1 = 3.402823466e38f;
    int bi0 = 0, bi1 = 0;

    for (int t = 0; t < K_CODES; t += TILE_K) {
        __syncthreads();
        // Cooperative duplicated-tile load: 4096 elements, each written as {v,v}.
        #pragma unroll
        for (int i = 0; i < 32; i++) {
            int u = tid + i * THREADS;          // 0..4095
            int c = u >> 6;
            int k = u & 63;
            float v = emb[(size_t)(t + c) * D + k];
            *(float2*)(sh_e + c * (2 * D) + 2 * k) = make_float2(v, v);
        }
        if (tid < TILE_K) sh_norm[tid] = g_norms[t + tid];
        __syncthreads();

        // Two codes in flight (independent packed chains) for ILP.
        for (int c = 0; c < TILE_K; c += 2) {
            const ulonglong2* pa = (const ulonglong2*)(sh_e + (c    ) * (2 * D));
            const ulonglong2* pb = (const ulonglong2*)(sh_e + (c + 1) * (2 * D));
            ull accA = 0ull, accB = 0ull;
            #pragma unroll
            for (int j = 0; j < 32; j++) {
                ulonglong2 ea = pa[j];          // LDS.128, uniform addr
                ulonglong2 eb = pb[j];
                fma2(accA, xp[2*j],   ea.x);    // lane0: row0 chain, lane1: row1
                fma2(accA, xp[2*j+1], ea.y);
                fma2(accB, xp[2*j],   eb.x);
                fma2(accB, xp[2*j+1], eb.y);
            }
            const float bnA = sh_norm[c];
            const float bnB = sh_norm[c + 1];
            float dA0, dA1, dB0, dB1;
            unpack2(accA, dA0, dA1);
            unpack2(accB, dB0, dB1);
            float distA0 = __fadd_rn(__fmaf_rn(-2.f, dA0, asq0), bnA);
            float distB0 = __fadd_rn(__fmaf_rn(-2.f, dB0, asq0), bnB);
            float distA1 = __fadd_rn(__fmaf_rn(-2.f, dA1, asq1), bnA);
            float distB1 = __fadd_rn(__fmaf_rn(-2.f, dB1, asq1), bnB);
            // Ascending order: code c before c+1 (first-index tie-break).
            if (distA0 < best0) { best0 = distA0; bi0 = t + c; }
            if (distB0 < best0) { best0 = distB0; bi0 = t + c + 1; }
            if (distA1 < best1) { best1 = distA1; bi1 = t + c; }
            if (distB1 < best1) { best1 = distB1; bi1 = t + c + 1; }
        }
    }

    // Epilogue: gather code rows, write quantized + indices, accumulate loss.
    float ls = 0.f;
    {
        const float4* eq0 = (const float4*)(emb + (size_t)bi0 * D);
        const float4* eq1 = (const float4*)(emb + (size_t)bi1 * D);
        float4* qo0 = (float4*)(out + (size_t)r0 * D);
        float4* qo1 = (float4*)(out + (size_t)r1 * D);
        #pragma unroll
        for (int i = 0; i < 16; i++) {
            float4 q0 = eq0[i];
            float4 q1 = eq1[i];
            float ax, bx, ay, by, az, bz, aw, bw;
            unpack2(xp[4*i+0], ax, bx);
            unpack2(xp[4*i+1], ay, by);
            unpack2(xp[4*i+2], az, bz);
            unpack2(xp[4*i+3], aw, bw);
            float d0 = ax - q0.x, d1 = ay - q0.y, d2 = az - q0.z, d3 = aw - q0.w;
            ls = fmaf(d0, d0, ls); ls = fmaf(d1, d1, ls);
            ls = fmaf(d2, d2, ls); ls = fmaf(d3, d3, ls);
            float e0 = bx - q1.x, e1 = by - q1.y, e2 = bz - q1.z, e3 = bw - q1.w;
            ls = fmaf(e0, e0, ls); ls = fmaf(e1, e1, ls);
            ls = fmaf(e2, e2, ls); ls = fmaf(e3, e3, ls);
            qo0[i] = q0;
            qo1[i] = q1;
        }
        out[QOFF + r0] = (float)bi0;
        out[QOFF + r1] = (float)bi1;
        atomicAdd(&g_hist[bi0], 1);
        atomicAdd(&g_hist[bi1], 1);
    }

    // Deterministic per-block loss partial.
    sh_red[tid] = ls;
    __syncthreads();
    for (int s = THREADS / 2; s > 0; s >>= 1) {
        if (tid < s) sh_red[tid] += sh_red[tid + s];
        __syncthreads();
    }
    if (tid == 0) g_partial[blockIdx.x] = sh_red[0];
}

// Perplexity + vq_loss (single block; deterministic tree reductions).
__global__ void vq_final_kernel(float* __restrict__ out) {
    __shared__ float sh[1024];
    const int t = threadIdx.x;

    float p = (float)g_hist[t] * (1.0f / (float)N_ROWS);
    sh[t] = p * logf(p + 1e-10f);
    __syncthreads();
    for (int s = 512; s > 0; s >>= 1) {
        if (t < s) sh[t] += sh[t + s];
        __syncthreads();
    }
    float ent = sh[0];
    __syncthreads();

    sh[t] = (t < NUM_BLOCKS) ? g_partial[t] : 0.f;
    __syncthreads();
    for (int s = 512; s > 0; s >>= 1) {
        if (t < s) sh[t] += sh[t + s];
        __syncthreads();
    }

    if (t == 0) {
        float m = sh[0] / (float)((size_t)N_ROWS * D);
        out[QOFF + N_ROWS]     = expf(-ent);       // perplexity
        out[QOFF + N_ROWS + 1] = m + 0.25f * m;    // commitment + beta*codebook
    }
}

extern "C" void kernel_launch(void* const* d_in, const int* in_sizes, int n_in,
                              void* d_out, int out_size) {
    const float* inp = (const float*)d_in[0];   // [131072, 64]
    const float* emb = (const float*)d_in[1];   // [1024, 64]
    float* out = (float*)d_out;

    vq_prep_kernel<<<4, 256>>>(emb);
    vq_main_kernel<<<NUM_BLOCKS, THREADS>>>(inp, emb, out);
    vq_final_kernel<<<1, 1024>>>(out);
}

// round 8
// speedup vs baseline: 1.5239x; 1.5239x over previous
#include <cuda_runtime.h>
#include <math.h>
#include <stdint.h>
#include <float.h>

// VQ_Layer — tf32 mma.sync filter + exact fp32 refine (sm_100 baseline ISA).
// Phase 1: approximate scores s = -2*dot + |e|^2 for all 131072x1024 pairs via
//   warp-level tf32 tensor-core mma; per row flag codes within EPS2=0.1 of the
//   row min (tf32 error 2*eps ~ 0.01 -> provable superset of exact argmin).
// Phase 2: re-evaluate flagged candidates with the R5-verified bit-exact
//   sequential-chain arithmetic; order-independent first-index tie-break.
//   >CAND_CAP candidates -> exact full scan (correctness never depends on cap).

typedef unsigned long long ull;

#define N_ROWS 131072
#define D 64
#define K_CODES 1024
#define QOFF (N_ROWS * D)

#define F_THREADS 128
#define F_ROWS 64
#define F_BLOCKS (N_ROWS / F_ROWS)         // 2048
#define CHUNK 128
#define NCHUNK (K_CODES / CHUNK)           // 8
#define BPITCH 68                          // smem B pitch (floats): bank-conflict-free
#define CAND_CAP 32
#define EPS2 0.1f

#define R_THREADS 256
#define R_BLOCKS (N_ROWS / R_THREADS)      // 512

// ---- device scratch (no allocations allowed) ----
__device__ float g_norms[K_CODES];
__device__ int   g_hist[K_CODES];
__device__ float g_partial[R_BLOCKS];
__device__ unsigned short g_cand[CAND_CAP * N_ROWS];   // 8 MB
__device__ int   g_cnt[N_ROWS];

// ---- helpers ----
__device__ __forceinline__ uint32_t f2tf32(float f) {
    uint32_t r; asm("cvt.rna.tf32.f32 %0, %1;" : "=r"(r) : "f"(f)); return r;
}
__device__ __forceinline__ void mma_tf32(float c[4], const uint32_t a[4],
                                         uint32_t b0, uint32_t b1) {
    asm("mma.sync.aligned.m16n8k8.row.col.f32.tf32.tf32.f32 "
        "{%0,%1,%2,%3}, {%4,%5,%6,%7}, {%8,%9}, {%0,%1,%2,%3};"
        : "+f"(c[0]), "+f"(c[1]), "+f"(c[2]), "+f"(c[3])
        : "r"(a[0]), "r"(a[1]), "r"(a[2]), "r"(a[3]), "r"(b0), "r"(b1));
}

// ---- exact-arithmetic helpers (R5-verified reference numerics) ----
__device__ __forceinline__ float exact_asq(const float4* x) {
    float s = 0.f;
    #pragma unroll
    for (int i = 0; i < 16; i++) {
        float4 v = x[i];
        s = __fadd_rn(s, __fmul_rn(v.x, v.x));
        s = __fadd_rn(s, __fmul_rn(v.y, v.y));
        s = __fadd_rn(s, __fmul_rn(v.z, v.z));
        s = __fadd_rn(s, __fmul_rn(v.w, v.w));
    }
    return s;
}
__device__ __forceinline__ float exact_dot(const float4* x, const float4* e) {
    float d = 0.f;
    #pragma unroll
    for (int j = 0; j < 16; j++) {
        float4 ev = e[j];
        float4 xv = x[j];
        d = __fmaf_rn(xv.x, ev.x, d);
        d = __fmaf_rn(xv.y, ev.y, d);
        d = __fmaf_rn(xv.z, ev.z, d);
        d = __fmaf_rn(xv.w, ev.w, d);
    }
    return d;
}

// ---- kernel 0: reset per-row counters + histogram ----
__global__ void vq_zero_kernel() {
    int i = blockIdx.x * blockDim.x + threadIdx.x;
    if (i < N_ROWS) g_cnt[i] = 0;
    if (i < K_CODES) g_hist[i] = 0;
}

// ---- kernel 1: exact code norms ----
__global__ void vq_prep_kernel(const float* __restrict__ emb) {
    int k = blockIdx.x * blockDim.x + threadIdx.x;
    if (k < K_CODES)
        g_norms[k] = exact_asq((const float4*)(emb + (size_t)k * D));
}

// ---- kernel 2: tf32 mma.sync filter ----
__global__ __launch_bounds__(F_THREADS) void vq_filter_kernel(
    const float* __restrict__ inp,
    const float* __restrict__ emb)
{
    __shared__ uint32_t shB[CHUNK * BPITCH];   // tf32 bits, [code][k], pitch 68
    __shared__ float sh_bn[K_CODES];

    const int tid = threadIdx.x;
    const int lane = tid & 31;
    const int w = tid >> 5;
    const int gq = lane >> 2;     // groupID (row within tile)
    const int tq = lane & 3;      // threadID in group
    const int grow0 = blockIdx.x * F_ROWS + w * 16 + gq;
    const int grow1 = grow0 + 8;

    for (int i = tid; i < K_CODES; i += F_THREADS) sh_bn[i] = g_norms[i];

    // A fragments: 16 rows x 64 k, tf32. a0:(g,tq) a1:(g+8,tq) a2:(g,tq+4) a3:(g+8,tq+4)
    uint32_t A[8][4];
    {
        const float* r0p = inp + (size_t)grow0 * D;
        const float* r1p = inp + (size_t)grow1 * D;
        #pragma unroll
        for (int ks = 0; ks < 8; ks++) {
            A[ks][0] = f2tf32(r0p[ks * 8 + tq]);
            A[ks][1] = f2tf32(r1p[ks * 8 + tq]);
            A[ks][2] = f2tf32(r0p[ks * 8 + tq + 4]);
            A[ks][3] = f2tf32(r1p[ks * 8 + tq + 4]);
        }
    }

    float best0 = FLT_MAX, best1 = FLT_MAX;

    for (int ch = 0; ch < NCHUNK; ch++) {
        __syncthreads();   // previous chunk's shB reads complete
        {
            // thread tid loads code ch*128+tid (64 floats), converts, stores
            const float4* src = (const float4*)(emb + (size_t)(ch * CHUNK + tid) * D);
            uint32_t* dst = &shB[tid * BPITCH];
            #pragma unroll
            for (int i = 0; i < 16; i++) {
                float4 v = src[i];
                dst[4*i+0] = f2tf32(v.x);
                dst[4*i+1] = f2tf32(v.y);
                dst[4*i+2] = f2tf32(v.z);
                dst[4*i+3] = f2tf32(v.w);
            }
        }
        __syncthreads();

        float c[16][4];
        #pragma unroll
        for (int nt = 0; nt < 16; nt++)
            c[nt][0] = c[nt][1] = c[nt][2] = c[nt][3] = 0.f;

        #pragma unroll
        for (int ks = 0; ks < 8; ks++) {
            #pragma unroll
            for (int nt = 0; nt < 16; nt++) {
                int n = nt * 8 + gq;
                uint32_t b0 = shB[n * BPITCH + ks * 8 + tq];
                uint32_t b1 = shB[n * BPITCH + ks * 8 + tq + 4];
                mma_tf32(c[nt], A[ks], b0, b1);
            }
        }

        // scores s = bn - 2*dot (asq omitted: constant per row, cancels in
        // both argmin and the eps-window). c0,c1 -> row0; c2,c3 -> row1.
        const int cbase = ch * CHUNK;
        float m0 = FLT_MAX, m1 = FLT_MAX;
        #pragma unroll
        for (int nt = 0; nt < 16; nt++) {
            int col0 = cbase + nt * 8 + 2 * tq;
            float bn0 = sh_bn[col0], bn1 = sh_bn[col0 + 1];
            float s00 = fmaf(-2.f, c[nt][0], bn0);
            float s01 = fmaf(-2.f, c[nt][1], bn1);
            float s10 = fmaf(-2.f, c[nt][2], bn0);
            float s11 = fmaf(-2.f, c[nt][3], bn1);
            c[nt][0] = s00; c[nt][1] = s01; c[nt][2] = s10; c[nt][3] = s11;
            m0 = fminf(m0, fminf(s00, s01));
            m1 = fminf(m1, fminf(s10, s11));
        }
        // quad-reduce row minima (lanes differing in tq bits 0,1)
        m0 = fminf(m0, __shfl_xor_sync(0xffffffffu, m0, 1));
        m0 = fminf(m0, __shfl_xor_sync(0xffffffffu, m0, 2));
        m1 = fminf(m1, __shfl_xor_sync(0xffffffffu, m1, 1));
        m1 = fminf(m1, __shfl_xor_sync(0xffffffffu, m1, 2));
        best0 = fminf(best0, m0);
        best1 = fminf(best1, m1);
        const float th0 = best0 + EPS2;
        const float th1 = best1 + EPS2;

        #pragma unroll
        for (int nt = 0; nt < 16; nt++) {
            int col0 = cbase + nt * 8 + 2 * tq;
            if (c[nt][0] <= th0) {
                int s = atomicAdd(&g_cnt[grow0], 1);
                if (s < CAND_CAP) g_cand[s * N_ROWS + grow0] = (unsigned short)col0;
            }
            if (c[nt][1] <= th0) {
                int s = atomicAdd(&g_cnt[grow0], 1);
                if (s < CAND_CAP) g_cand[s * N_ROWS + grow0] = (unsigned short)(col0 + 1);
            }
            if (c[nt][2] <= th1) {
                int s = atomicAdd(&g_cnt[grow1], 1);
                if (s < CAND_CAP) g_cand[s * N_ROWS + grow1] = (unsigned short)col0;
            }
            if (c[nt][3] <= th1) {
                int s = atomicAdd(&g_cnt[grow1], 1);
                if (s < CAND_CAP) g_cand[s * N_ROWS + grow1] = (unsigned short)(col0 + 1);
            }
        }
    }
}

// ---- kernel 3: exact refine + outputs ----
__global__ __launch_bounds__(R_THREADS) void vq_refine_kernel(
    const float* __restrict__ inp,
    const float* __restrict__ emb,
    float* __restrict__ out)
{
    __shared__ float sh_red[R_THREADS];
    const int tid = threadIdx.x;
    const int r = blockIdx.x * R_THREADS + tid;

    float4 x[16];
    {
        const float4* p = (const float4*)(inp + (size_t)r * D);
        #pragma unroll
        for (int i = 0; i < 16; i++) x[i] = p[i];
    }
    const float asq = exact_asq(x);

    int bi = K_CODES;
    float best = FLT_MAX;
    int cnt = g_cnt[r];
    if (cnt > CAND_CAP) {
        // overflow fallback: exact full scan, ascending (first-index ties)
        for (int c = 0; c < K_CODES; c++) {
            float dot = exact_dot(x, (const float4*)(emb + (size_t)c * D));
            float dist = __fadd_rn(__fmaf_rn(-2.f, dot, asq), g_norms[c]);
            if (dist < best) { best = dist; bi = c; }
        }
    } else {
        // candidate order is arbitrary (atomic append): order-independent
        // tie-break = smallest index among exact minima.
        for (int i = 0; i < cnt; i++) {
            int c = g_cand[i * N_ROWS + r];
            float dot = exact_dot(x, (const float4*)(emb + (size_t)c * D));
            float dist = __fadd_rn(__fmaf_rn(-2.f, dot, asq), g_norms[c]);
            if (dist < best || (dist == best && c < bi)) { best = dist; bi = c; }
        }
    }

    // epilogue: quantized row, index, loss, histogram
    float ls = 0.f;
    {
        const float4* eq = (const float4*)(emb + (size_t)bi * D);
        float4* qo = (float4*)(out + (size_t)r * D);
        #pragma unroll
        for (int i = 0; i < 16; i++) {
            float4 q = eq[i];
            float4 v = x[i];
            float d0 = v.x - q.x, d1 = v.y - q.y, d2 = v.z - q.z, d3 = v.w - q.w;
            ls = fmaf(d0, d0, ls); ls = fmaf(d1, d1, ls);
            ls = fmaf(d2, d2, ls); ls = fmaf(d3, d3, ls);
            qo[i] = q;
        }
        out[QOFF + r] = (float)bi;
        atomicAdd(&g_hist[bi], 1);
    }

    sh_red[tid] = ls;
    __syncthreads();
    for (int s = R_THREADS / 2; s > 0; s >>= 1) {
        if (tid < s) sh_red[tid] += sh_red[tid + s];
        __syncthreads();
    }
    if (tid == 0) g_partial[blockIdx.x] = sh_red[0];
}

// ---- kernel 4: perplexity + vq_loss ----
__global__ void vq_final_kernel(float* __restrict__ out) {
    __shared__ float sh[1024];
    const int t = threadIdx.x;

    float p = (float)g_hist[t] * (1.0f / (float)N_ROWS);
    sh[t] = p * logf(p + 1e-10f);
    __syncthreads();
    for (int s = 512; s > 0; s >>= 1) {
        if (t < s) sh[t] += sh[t + s];
        __syncthreads();
    }
    float ent = sh[0];
    __syncthreads();

    sh[t] = (t < R_BLOCKS) ? g_partial[t] : 0.f;
    __syncthreads();
    for (int s = 512; s > 0; s >>= 1) {
        if (t < s) sh[t] += sh[t + s];
        __syncthreads();
    }

    if (t == 0) {
        float m = sh[0] / (float)((size_t)N_ROWS * D);
        out[QOFF + N_ROWS]     = expf(-ent);       // perplexity
        out[QOFF + N_ROWS + 1] = m + 0.25f * m;    // commitment + beta*codebook
    }
}

extern "C" void kernel_launch(void* const* d_in, const int* in_sizes, int n_in,
                              void* d_out, int out_size) {
    const float* inp = (const float*)d_in[0];   // [131072, 64]
    const float* emb = (const float*)d_in[1];   // [1024, 64]
    float* out = (float*)d_out;

    vq_zero_kernel<<<512, 256>>>();
    vq_prep_kernel<<<4, 256>>>(emb);
    vq_filter_kernel<<<F_BLOCKS, F_THREADS>>>(inp, emb);
    vq_refine_kernel<<<R_BLOCKS, R_THREADS>>>(inp, emb, out);
    vq_final_kernel<<<1, 1024>>>(out);
}

// round 12
// speedup vs baseline: 1.6940x; 1.1116x over previous
#include <cuda_runtime.h>
#include <cuda_fp16.h>
#include <math.h>
#include <stdint.h>
#include <float.h>

// VQ_Layer — fp16 mma.sync filter + exact fp32 refine (sm_100 baseline ISA).
// Phase 1: approximate scores s = -2*dot + |e|^2 for all 131072x1024 pairs via
//   m16n8k16 fp16 tensor mma (fp32 accum); per row flag codes within EPS2=0.1
//   of the row min (fp16-input error bound ~0.04 worst case -> superset of the
//   exact argmin). Phase 2: re-evaluate flagged candidates with the
//   R5-verified bit-exact sequential-chain arithmetic; order-independent
//   first-index tie-break. >CAND_CAP candidates -> exact full scan, so
//   correctness never depends on the cap.

typedef unsigned long long ull;

#define N_ROWS 131072
#define D 64
#define K_CODES 1024
#define QOFF (N_ROWS * D)

#define F_THREADS 128
#define F_ROWS 64
#define F_BLOCKS (N_ROWS / F_ROWS)         // 2048
#define CHUNK 128
#define NCHUNK (K_CODES / CHUNK)           // 8
#define BPITCH 36                          // words per code in shB (72 halves)
#define CAND_CAP 32
#define EPS2 0.1f

#define R_THREADS 256
#define R_BLOCKS (N_ROWS / R_THREADS)      // 512

// ---- device scratch (no allocations allowed) ----
__device__ float g_norms[K_CODES];
__device__ int   g_hist[K_CODES];
__device__ float g_partial[R_BLOCKS];
__device__ unsigned short g_cand[CAND_CAP * N_ROWS];   // 8 MB
__device__ int   g_cnt[N_ROWS];

// ---- helpers ----
__device__ __forceinline__ uint32_t h2(float lo, float hi) {
    __half2 h = __floats2half2_rn(lo, hi);
    return *(uint32_t*)&h;
}
__device__ __forceinline__ void mma_f16(float c[4], const uint32_t a[4],
                                        uint32_t b0, uint32_t b1) {
    asm("mma.sync.aligned.m16n8k16.row.col.f32.f16.f16.f32 "
        "{%0,%1,%2,%3}, {%4,%5,%6,%7}, {%8,%9}, {%0,%1,%2,%3};"
        : "+f"(c[0]), "+f"(c[1]), "+f"(c[2]), "+f"(c[3])
        : "r"(a[0]), "r"(a[1]), "r"(a[2]), "r"(a[3]), "r"(b0), "r"(b1));
}

// ---- exact-arithmetic helpers (R5-verified reference numerics) ----
__device__ __forceinline__ float exact_asq(const float4* x) {
    float s = 0.f;
    #pragma unroll
    for (int i = 0; i < 16; i++) {
        float4 v = x[i];
        s = __fadd_rn(s, __fmul_rn(v.x, v.x));
        s = __fadd_rn(s, __fmul_rn(v.y, v.y));
        s = __fadd_rn(s, __fmul_rn(v.z, v.z));
        s = __fadd_rn(s, __fmul_rn(v.w, v.w));
    }
    return s;
}
__device__ __forceinline__ float exact_dot(const float4* x, const float4* e) {
    float d = 0.f;
    #pragma unroll
    for (int j = 0; j < 16; j++) {
        float4 ev = e[j];
        float4 xv = x[j];
        d = __fmaf_rn(xv.x, ev.x, d);
        d = __fmaf_rn(xv.y, ev.y, d);
        d = __fmaf_rn(xv.z, ev.z, d);
        d = __fmaf_rn(xv.w, ev.w, d);
    }
    return d;
}

// ---- kernel 0: reset per-row counters + histogram ----
__global__ void vq_zero_kernel() {
    int i = blockIdx.x * blockDim.x + threadIdx.x;
    if (i < N_ROWS) g_cnt[i] = 0;
    if (i < K_CODES) g_hist[i] = 0;
}

// ---- kernel 1: exact code norms ----
__global__ void vq_prep_kernel(const float* __restrict__ emb) {
    int k = blockIdx.x * blockDim.x + threadIdx.x;
    if (k < K_CODES)
        g_norms[k] = exact_asq((const float4*)(emb + (size_t)k * D));
}

// ---- kernel 2: fp16 mma.sync filter ----
__global__ __launch_bounds__(F_THREADS) void vq_filter_kernel(
    const float* __restrict__ inp,
    const float* __restrict__ emb)
{
    __shared__ uint32_t shB[CHUNK * BPITCH];   // half2 words, [code][k/2], pitch 36
    __shared__ float sh_bn[K_CODES];

    const int tid = threadIdx.x;
    const int lane = tid & 31;
    const int w = tid >> 5;
    const int gq = lane >> 2;     // groupID (row within tile / col gq for B)
    const int tq = lane & 3;      // threadID in group
    const int grow0 = blockIdx.x * F_ROWS + w * 16 + gq;
    const int grow1 = grow0 + 8;

    for (int i = tid; i < K_CODES; i += F_THREADS) sh_bn[i] = g_norms[i];

    // A fragments (m16n8k16): per ks (k-chunk of 16):
    //   a0: (row gq,   k=ks*16+2tq,2tq+1)  a1: (row gq+8, same k)
    //   a2: (row gq,   k=+8)               a3: (row gq+8, k=+8)
    uint32_t A[4][4];
    {
        const float2* r0p = (const float2*)(inp + (size_t)grow0 * D);
        const float2* r1p = (const float2*)(inp + (size_t)grow1 * D);
        #pragma unroll
        for (int ks = 0; ks < 4; ks++) {
            float2 v;
            v = r0p[ks * 8 + tq];     A[ks][0] = h2(v.x, v.y);
            v = r1p[ks * 8 + tq];     A[ks][1] = h2(v.x, v.y);
            v = r0p[ks * 8 + 4 + tq]; A[ks][2] = h2(v.x, v.y);
            v = r1p[ks * 8 + 4 + tq]; A[ks][3] = h2(v.x, v.y);
        }
    }

    float best0 = FLT_MAX, best1 = FLT_MAX;

    for (int ch = 0; ch < NCHUNK; ch++) {
        __syncthreads();   // previous chunk's shB reads complete
        {
            // thread tid loads code ch*128+tid (64 floats) -> half2 words
            const float4* src = (const float4*)(emb + (size_t)(ch * CHUNK + tid) * D);
            uint32_t* dst = &shB[tid * BPITCH];
            #pragma unroll
            for (int i = 0; i < 16; i++) {
                float4 v = src[i];
                dst[2*i]   = h2(v.x, v.y);
                dst[2*i+1] = h2(v.z, v.w);
            }
        }
        __syncthreads();

        float c[16][4];
        #pragma unroll
        for (int nt = 0; nt < 16; nt++)
            c[nt][0] = c[nt][1] = c[nt][2] = c[nt][3] = 0.f;

        #pragma unroll
        for (int ks = 0; ks < 4; ks++) {
            #pragma unroll
            for (int nt = 0; nt < 16; nt++) {
                int n = nt * 8 + gq;
                // b0: k = ks*16 + 2tq (word ks*8+tq); b1: k = +8 (word +4)
                uint32_t b0 = shB[n * BPITCH + ks * 8 + tq];
                uint32_t b1 = shB[n * BPITCH + ks * 8 + 4 + tq];
                mma_f16(c[nt], A[ks], b0, b1);
            }
        }

        // scores s = bn - 2*dot (asq constant per row: cancels in argmin and
        // in the eps-window). c0,c1 -> row gq; c2,c3 -> row gq+8.
        const int cbase = ch * CHUNK;
        float m0 = FLT_MAX, m1 = FLT_MAX;
        #pragma unroll
        for (int nt = 0; nt < 16; nt++) {
            int col0 = cbase + nt * 8 + 2 * tq;
            float bn0 = sh_bn[col0], bn1 = sh_bn[col0 + 1];
            float s00 = fmaf(-2.f, c[nt][0], bn0);
            float s01 = fmaf(-2.f, c[nt][1], bn1);
            float s10 = fmaf(-2.f, c[nt][2], bn0);
            float s11 = fmaf(-2.f, c[nt][3], bn1);
            c[nt][0] = s00; c[nt][1] = s01; c[nt][2] = s10; c[nt][3] = s11;
            m0 = fminf(m0, fminf(s00, s01));
            m1 = fminf(m1, fminf(s10, s11));
        }
        // quad-reduce row minima (lanes differing in tq bits)
        m0 = fminf(m0, __shfl_xor_sync(0xffffffffu, m0, 1));
        m0 = fminf(m0, __shfl_xor_sync(0xffffffffu, m0, 2));
        m1 = fminf(m1, __shfl_xor_sync(0xffffffffu, m1, 1));
        m1 = fminf(m1, __shfl_xor_sync(0xffffffffu, m1, 2));
        best0 = fminf(best0, m0);
        best1 = fminf(best1, m1);
        const float th0 = best0 + EPS2;
        const float th1 = best1 + EPS2;

        #pragma unroll
        for (int nt = 0; nt < 16; nt++) {
            int col0 = cbase + nt * 8 + 2 * tq;
            if (c[nt][0] <= th0) {
                int s = atomicAdd(&g_cnt[grow0], 1);
                if (s < CAND_CAP) g_cand[s * N_ROWS + grow0] = (unsigned short)col0;
            }
            if (c[nt][1] <= th0) {
                int s = atomicAdd(&g_cnt[grow0], 1);
                if (s < CAND_CAP) g_cand[s * N_ROWS + grow0] = (unsigned short)(col0 + 1);
            }
            if (c[nt][2] <= th1) {
                int s = atomicAdd(&g_cnt[grow1], 1);
                if (s < CAND_CAP) g_cand[s * N_ROWS + grow1] = (unsigned short)col0;
            }
            if (c[nt][3] <= th1) {
                int s = atomicAdd(&g_cnt[grow1], 1);
                if (s < CAND_CAP) g_cand[s * N_ROWS + grow1] = (unsigned short)(col0 + 1);
            }
        }
    }
}

// ---- kernel 3: exact refine + outputs (ILP-2 over candidates) ----
__global__ __launch_bounds__(R_THREADS) void vq_refine_kernel(
    const float* __restrict__ inp,
    const float* __restrict__ emb,
    float* __restrict__ out)
{
    __shared__ float sh_red[R_THREADS];
    const int tid = threadIdx.x;
    const int r = blockIdx.x * R_THREADS + tid;

    float4 x[16];
    {
        const float4* p = (const float4*)(inp + (size_t)r * D);
        #pragma unroll
        for (int i = 0; i < 16; i++) x[i] = p[i];
    }
    const float asq = exact_asq(x);

    int bi = K_CODES;
    float best = FLT_MAX;
    int cnt = g_cnt[r];
    if (cnt > CAND_CAP) {
        // overflow fallback: exact full scan, ascending with ILP-2
        // (compare c before c+1 -> first-index tie-break preserved)
        for (int c = 0; c < K_CODES; c += 2) {
            float dotA = 0.f, dotB = 0.f;
            const float4* ea = (const float4*)(emb + (size_t)c * D);
            const float4* eb = ea + 16;
            #pragma unroll
            for (int j = 0; j < 16; j++) {
                float4 va = ea[j], vb = eb[j], xv = x[j];
                dotA = __fmaf_rn(xv.x, va.x, dotA);
                dotB = __fmaf_rn(xv.x, vb.x, dotB);
                dotA = __fmaf_rn(xv.y, va.y, dotA);
                dotB = __fmaf_rn(xv.y, vb.y, dotB);
                dotA = __fmaf_rn(xv.z, va.z, dotA);
                dotB = __fmaf_rn(xv.z, vb.z, dotB);
                dotA = __fmaf_rn(xv.w, va.w, dotA);
                dotB = __fmaf_rn(xv.w, vb.w, dotB);
            }
            float dA = __fadd_rn(__fmaf_rn(-2.f, dotA, asq), g_norms[c]);
            float dB = __fadd_rn(__fmaf_rn(-2.f, dotB, asq), g_norms[c + 1]);
            if (dA < best) { best = dA; bi = c; }
            if (dB < best) { best = dB; bi = c + 1; }
        }
    } else {
        // candidate order arbitrary (atomic append): order-independent
        // tie-break = smallest index among exact minima. ILP-2 pairs.
        int i = 0;
        for (; i + 1 < cnt; i += 2) {
            int cA = g_cand[i * N_ROWS + r];
            int cB = g_cand[(i + 1) * N_ROWS + r];
            const float4* ea = (const float4*)(emb + (size_t)cA * D);
            const float4* eb = (const float4*)(emb + (size_t)cB * D);
            float dotA = 0.f, dotB = 0.f;
            #pragma unroll
            for (int j = 0; j < 16; j++) {
                float4 va = ea[j], vb = eb[j], xv = x[j];
                dotA = __fmaf_rn(xv.x, va.x, dotA);
                dotB = __fmaf_rn(xv.x, vb.x, dotB);
                dotA = __fmaf_rn(xv.y, va.y, dotA);
                dotB = __fmaf_rn(xv.y, vb.y, dotB);
                dotA = __fmaf_rn(xv.z, va.z, dotA);
                dotB = __fmaf_rn(xv.z, vb.z, dotB);
                dotA = __fmaf_rn(xv.w, va.w, dotA);
                dotB = __fmaf_rn(xv.w, vb.w, dotB);
            }
            float dA = __fadd_rn(__fmaf_rn(-2.f, dotA, asq), g_norms[cA]);
            float dB = __fadd_rn(__fmaf_rn(-2.f, dotB, asq), g_norms[cB]);
            if (dA < best || (dA == best && cA < bi)) { best = dA; bi = cA; }
            if (dB < best || (dB == best && cB < bi)) { best = dB; bi = cB; }
        }
        if (i < cnt) {
            int c = g_cand[i * N_ROWS + r];
            float dot = exact_dot(x, (const float4*)(emb + (size_t)c * D));
            float dist = __fadd_rn(__fmaf_rn(-2.f, dot, asq), g_norms[c]);
            if (dist < best || (dist == best && c < bi)) { best = dist; bi = c; }
        }
    }

    // epilogue: quantized row, index, loss, histogram
    float ls = 0.f;
    {
        const float4* eq = (const float4*)(emb + (size_t)bi * D);
        float4* qo = (float4*)(out + (size_t)r * D);
        #pragma unroll
        for (int i = 0; i < 16; i++) {
            float4 q = eq[i];
            float4 v = x[i];
            float d0 = v.x - q.x, d1 = v.y - q.y, d2 = v.z - q.z, d3 = v.w - q.w;
            ls = fmaf(d0, d0, ls); ls = fmaf(d1, d1, ls);
            ls = fmaf(d2, d2, ls); ls = fmaf(d3, d3, ls);
            qo[i] = q;
        }
        out[QOFF + r] = (float)bi;
        atomicAdd(&g_hist[bi], 1);
    }

    sh_red[tid] = ls;
    __syncthreads();
    for (int s = R_THREADS / 2; s > 0; s >>= 1) {
        if (tid < s) sh_red[tid] += sh_red[tid + s];
        __syncthreads();
    }
    if (tid == 0) g_partial[blockIdx.x] = sh_red[0];
}

// ---- kernel 4: perplexity + vq_loss ----
__global__ void vq_final_kernel(float* __restrict__ out) {
    __shared__ float sh[1024];
    const int t = threadIdx.x;

    float p = (float)g_hist[t] * (1.0f / (float)N_ROWS);
    sh[t] = p * logf(p + 1e-10f);
    __syncthreads();
    for (int s = 512; s > 0; s >>= 1) {
        if (t < s) sh[t] += sh[t + s];
        __syncthreads();
    }
    float ent = sh[0];
    __syncthreads();

    sh[t] = (t < R_BLOCKS) ? g_partial[t] : 0.f;
    __syncthreads();
    for (int s = 512; s > 0; s >>= 1) {
        if (t < s) sh[t] += sh[t + s];
        __syncthreads();
    }

    if (t == 0) {
        float m = sh[0] / (float)((size_t)N_ROWS * D);
        out[QOFF + N_ROWS]     = expf(-ent);       // perplexity
        out[QOFF + N_ROWS + 1] = m + 0.25f * m;    // commitment + beta*codebook
    }
}

extern "C" void kernel_launch(void* const* d_in, const int* in_sizes, int n_in,
                              void* d_out, int out_size) {
    const float* inp = (const float*)d_in[0];   // [131072, 64]
    const float* emb = (const float*)d_in[1];   // [1024, 64]
    float* out = (float*)d_out;

    vq_zero_kernel<<<512, 256>>>();
    vq_prep_kernel<<<4, 256>>>(emb);
    vq_filter_kernel<<<F_BLOCKS, F_THREADS>>>(inp, emb);
    vq_refine_kernel<<<R_BLOCKS, R_THREADS>>>(inp, emb, out);
    vq_final_kernel<<<1, 1024>>>(out);
}